// round 3
// baseline (speedup 1.0000x reference)
#include <cuda_runtime.h>

// Problem constants
#define T_STEPS 1024
#define BATCH   32
#define IN_DIM  1024
#define NHEAD   8
#define HSZ     128
#define G4      512            // 4*HS rows per head
#define NCOL    4096           // NH * 4 * HS
#define KDIM    1024           // input size (GEMM K)

// 512 MB scratch for the precomputed input projection lin_x[t, b, n]
__device__ float g_linx[(size_t)T_STEPS * BATCH * NCOL];

// ---------------- packed f32x2 helpers (Blackwell dual-FP32 path) ----------
__device__ __forceinline__ unsigned long long pk(float lo, float hi) {
    unsigned long long r;
    asm("mov.b64 %0, {%1, %2};"
        : "=l"(r) : "r"(__float_as_uint(lo)), "r"(__float_as_uint(hi)));
    return r;
}
__device__ __forceinline__ void fma2(unsigned long long& d,
                                     unsigned long long a,
                                     unsigned long long b) {
    asm("fma.rn.f32x2 %0, %1, %2, %0;" : "+l"(d) : "l"(a), "l"(b));
}
__device__ __forceinline__ float2 upk(unsigned long long v) {
    unsigned int lo, hi;
    asm("mov.b64 {%0, %1}, %2;" : "=r"(lo), "=r"(hi) : "l"(v));
    return make_float2(__uint_as_float(lo), __uint_as_float(hi));
}

// ============================================================================
// Phase 1: C[m][n] = sum_k A[m][k] * B[n][k]
//   A = xs   [M=32768, K=1024] row-major
//   B = W_ih [N=4096,  K=1024] row-major  (NT GEMM)
// 128x128 tile, BK=16, 256 threads, 8x8 per-thread micro-tile, f32x2 FMA,
// register-prefetch double-buffered SMEM.
// ============================================================================
#define BM 128
#define BN 128
#define BK 16

__global__ __launch_bounds__(256, 2)
void gemm_ih(const float* __restrict__ A,
             const float* __restrict__ B,
             float* __restrict__ C) {
    __shared__ float As[2][BK][BM];
    __shared__ float Bs[2][BK][BN];

    const int t  = threadIdx.x;
    const int m0 = (t >> 4) << 3;   // (t/16)*8
    const int n0 = (t & 15) << 3;   // (t%16)*8

    const float* Ap = A + (size_t)blockIdx.y * BM * KDIM;
    const float* Bp = B + (size_t)blockIdx.x * BN * KDIM;

    // each thread loads 2 float4 from A and 2 from B per K-tile
    const int p0 = t, p1 = t + 256;
    const int r0 = p0 >> 2, c0 = (p0 & 3) << 2;
    const int r1 = p1 >> 2, c1 = (p1 & 3) << 2;

    float4 ra0, ra1, rb0, rb1;

    auto ldAB = [&](int kt) {
        const size_t ko = (size_t)kt * BK;
        ra0 = *(const float4*)(Ap + (size_t)r0 * KDIM + ko + c0);
        ra1 = *(const float4*)(Ap + (size_t)r1 * KDIM + ko + c1);
        rb0 = *(const float4*)(Bp + (size_t)r0 * KDIM + ko + c0);
        rb1 = *(const float4*)(Bp + (size_t)r1 * KDIM + ko + c1);
    };
    auto stAB = [&](int b) {
        As[b][c0+0][r0] = ra0.x; As[b][c0+1][r0] = ra0.y;
        As[b][c0+2][r0] = ra0.z; As[b][c0+3][r0] = ra0.w;
        As[b][c1+0][r1] = ra1.x; As[b][c1+1][r1] = ra1.y;
        As[b][c1+2][r1] = ra1.z; As[b][c1+3][r1] = ra1.w;
        Bs[b][c0+0][r0] = rb0.x; Bs[b][c0+1][r0] = rb0.y;
        Bs[b][c0+2][r0] = rb0.z; Bs[b][c0+3][r0] = rb0.w;
        Bs[b][c1+0][r1] = rb1.x; Bs[b][c1+1][r1] = rb1.y;
        Bs[b][c1+2][r1] = rb1.z; Bs[b][c1+3][r1] = rb1.w;
    };

    unsigned long long acc[8][4];
    #pragma unroll
    for (int i = 0; i < 8; ++i)
        #pragma unroll
        for (int jj = 0; jj < 4; ++jj) acc[i][jj] = 0ull;

    ldAB(0);
    stAB(0);
    __syncthreads();

    int buf = 0;
    const int NKT = KDIM / BK;   // 64
    for (int kt = 0; kt < NKT; ++kt) {
        if (kt + 1 < NKT) ldAB(kt + 1);

        #pragma unroll
        for (int kk = 0; kk < BK; ++kk) {
            const float4 av0 = *(const float4*)&As[buf][kk][m0];
            const float4 av1 = *(const float4*)&As[buf][kk][m0 + 4];
            const float4 bv0 = *(const float4*)&Bs[buf][kk][n0];
            const float4 bv1 = *(const float4*)&Bs[buf][kk][n0 + 4];
            const unsigned long long bp0 = pk(bv0.x, bv0.y);
            const unsigned long long bp1 = pk(bv0.z, bv0.w);
            const unsigned long long bp2 = pk(bv1.x, bv1.y);
            const unsigned long long bp3 = pk(bv1.z, bv1.w);
            const float av[8] = {av0.x, av0.y, av0.z, av0.w,
                                 av1.x, av1.y, av1.z, av1.w};
            #pragma unroll
            for (int i = 0; i < 8; ++i) {
                const unsigned long long ad = pk(av[i], av[i]);
                fma2(acc[i][0], ad, bp0);
                fma2(acc[i][1], ad, bp1);
                fma2(acc[i][2], ad, bp2);
                fma2(acc[i][3], ad, bp3);
            }
        }

        if (kt + 1 < NKT) {
            stAB(buf ^ 1);
            __syncthreads();
            buf ^= 1;
        }
    }

    float* Cp = C + ((size_t)blockIdx.y * BM + m0) * NCOL
                  + (size_t)blockIdx.x * BN + n0;
    #pragma unroll
    for (int i = 0; i < 8; ++i) {
        const float2 x0 = upk(acc[i][0]);
        const float2 x1 = upk(acc[i][1]);
        const float2 x2 = upk(acc[i][2]);
        const float2 x3 = upk(acc[i][3]);
        *(float4*)(Cp + (size_t)i * NCOL)     = make_float4(x0.x, x0.y, x1.x, x1.y);
        *(float4*)(Cp + (size_t)i * NCOL + 4) = make_float4(x2.x, x2.y, x3.x, x3.y);
    }
}

// ============================================================================
// Phase 2: sequential sLSTM recurrence.
// Grid = 128 CTAs, clusters of 2 (the two halves of each head's 4*HS rows).
//   blockIdx.x: pair = bx>>1 -> head = pair&7, batch-group = pair>>3 (4 batches)
//               half = bx&1  -> output dims d in [half*64, half*64+64) per gate
// 256 threads: thread t owns gate g = t/64, row offset dr = t%64, i.e. one full
// W_hh row (128 fp32) pre-packed as 64 f32x2 pairs in registers.
// h state (4 batches x 128) lives in double-buffered SMEM; each CTA computes
// its 64-dim half of h_new and pushes it to the peer via st.shared::cluster,
// synchronized by barrier.cluster every step.
// ============================================================================
__global__ __launch_bounds__(256, 1) __cluster_dims__(2, 1, 1)
void slstm_rec(const float* __restrict__ Whh,   // [NH, 512, 128]
               const float* __restrict__ bias,  // [NH, 512]
               const float* __restrict__ linx,  // [T, B, 4096]
               float* __restrict__ out) {       // [T, B, 1024]
    __shared__ __align__(16) float hsh[2][4][HSZ];  // [buf][batch][j]
    __shared__ float gsh[4][4][64];                 // [gate][batch][d]

    const int bx   = blockIdx.x;
    const int half = bx & 1;
    const int pair = bx >> 1;
    const int head = pair & 7;
    const int bg   = pair >> 3;

    const int t  = threadIdx.x;
    const int g  = t >> 6;
    const int dr = t & 63;
    const int k  = g * HSZ + half * 64 + dr;   // row in [0, 512)

    // load + pre-pack this thread's W_hh row (64 f32x2 pairs in registers)
    const float4* wv = (const float4*)(Whh + ((size_t)head * G4 + k) * HSZ);
    unsigned long long wp[64];
    #pragma unroll
    for (int q = 0; q < 32; ++q) {
        const float4 v = wv[q];
        wp[2 * q]     = pk(v.x, v.y);
        wp[2 * q + 1] = pk(v.z, v.w);
    }
    const float bk = bias[head * G4 + k];

    // pointwise-phase identity: this thread owns state for (batch b2, dim d)
    const int b2     = t >> 6;
    const int d      = t & 63;
    const int j      = half * 64 + d;
    const int bglob  = bg * 4 + b2;
    const int outcol = head * HSZ + j;

    // zero both h buffers
    for (int z = t; z < 2 * 4 * HSZ; z += 256) ((float*)hsh)[z] = 0.f;

    // peer CTA's hsh base address (distributed shared memory)
    unsigned int lbase = (unsigned int)__cvta_generic_to_shared(&hsh[0][0][0]);
    unsigned int rbase;
    const unsigned int peer = (unsigned int)(half ^ 1);
    asm("mapa.shared::cluster.u32 %0, %1, %2;" : "=r"(rbase) : "r"(lbase), "r"(peer));

    float c_ = 0.f, m_ = 0.f, n_ = 0.f;

    asm volatile("barrier.cluster.arrive.aligned;" ::: "memory");
    asm volatile("barrier.cluster.wait.aligned;" ::: "memory");

    int cur = 0;
    const float* lxbase = linx + (size_t)(bg * 4) * NCOL + (size_t)head * G4 + k;

    #pragma unroll 1
    for (int ts = 0; ts < T_STEPS; ++ts) {
        // issue lin_x loads early (no dependency on h) so GEMM hides latency
        const float* lp = lxbase + (size_t)ts * ((size_t)BATCH * NCOL);
        const float lx0 = __ldg(lp);
        const float lx1 = __ldg(lp + NCOL);
        const float lx2 = __ldg(lp + 2 * NCOL);
        const float lx3 = __ldg(lp + 3 * NCOL);

        // dot(W_hh[k], h_prev) for 4 batches, packed f32x2
        unsigned long long a0 = 0ull, a1 = 0ull, a2 = 0ull, a3 = 0ull;
        #pragma unroll
        for (int q4 = 0; q4 < 32; ++q4) {
            const ulonglong2 h0 = *(const ulonglong2*)&hsh[cur][0][q4 * 4];
            fma2(a0, wp[2 * q4], h0.x); fma2(a0, wp[2 * q4 + 1], h0.y);
            const ulonglong2 h1 = *(const ulonglong2*)&hsh[cur][1][q4 * 4];
            fma2(a1, wp[2 * q4], h1.x); fma2(a1, wp[2 * q4 + 1], h1.y);
            const ulonglong2 h2 = *(const ulonglong2*)&hsh[cur][2][q4 * 4];
            fma2(a2, wp[2 * q4], h2.x); fma2(a2, wp[2 * q4 + 1], h2.y);
            const ulonglong2 h3 = *(const ulonglong2*)&hsh[cur][3][q4 * 4];
            fma2(a3, wp[2 * q4], h3.x); fma2(a3, wp[2 * q4 + 1], h3.y);
        }
        const float2 s0 = upk(a0), s1 = upk(a1), s2 = upk(a2), s3 = upk(a3);
        gsh[g][0][dr] = s0.x + s0.y + lx0 + bk;
        gsh[g][1][dr] = s1.x + s1.y + lx1 + bk;
        gsh[g][2][dr] = s2.x + s2.y + lx2 + bk;
        gsh[g][3][dr] = s3.x + s3.y + lx3 + bk;
        __syncthreads();

        // pointwise state update for (b2, d)
        const float iv = gsh[0][b2][d];
        const float fv = gsh[1][b2][d];
        const float zv = gsh[2][b2][d];
        const float ov = gsh[3][b2][d];

        const float zt = 1.f - 2.f / (__expf(2.f * zv) + 1.f);   // tanh
        const float os = 1.f / (1.f + __expf(-ov));              // sigmoid
        const float fm = fv + m_;
        const float mn = fmaxf(fm, iv);
        const float ie = __expf(iv - mn);
        const float fe = __expf(fm - mn);
        c_ = fe * c_ + ie * zt;
        n_ = fe * n_ + ie;
        m_ = mn;
        const float h = os * (c_ / n_);

        const int nxt = cur ^ 1;
        hsh[nxt][b2][j] = h;                                     // own copy
        const unsigned int roff =
            ((unsigned int)((nxt * 4 + b2) * HSZ + j)) * 4u;     // peer copy
        asm volatile("st.shared::cluster.f32 [%0], %1;"
                     :: "r"(rbase + roff), "f"(h) : "memory");

        out[((size_t)ts * BATCH + bglob) * (NHEAD * HSZ) + outcol] = h;

        // release our h writes / acquire peer's before next step reads hsh[nxt]
        asm volatile("barrier.cluster.arrive.aligned;" ::: "memory");
        asm volatile("barrier.cluster.wait.aligned;" ::: "memory");
        cur = nxt;
    }
}

// ============================================================================
extern "C" void kernel_launch(void* const* d_in, const int* in_sizes, int n_in,
                              void* d_out, int out_size) {
    const float* xs   = (const float*)d_in[0];  // [T, B, I]
    const float* wih  = (const float*)d_in[1];  // [NH, 4*HS, I]
    const float* whh  = (const float*)d_in[2];  // [NH, 4*HS, HS]
    const float* bias = (const float*)d_in[3];  // [NH, 4*HS]
    float* out = (float*)d_out;                 // [T, B, H]

    float* linx = nullptr;
    cudaGetSymbolAddress((void**)&linx, g_linx);

    dim3 g1(NCOL / BN, (T_STEPS * BATCH) / BM);  // (32, 256)
    gemm_ih<<<g1, 256>>>(xs, wih, linx);
    slstm_rec<<<128, 256>>>(whh, bias, linx, out);
}

// round 6
// speedup vs baseline: 1.8385x; 1.8385x over previous
#include <cuda_runtime.h>
#include <cuda_bf16.h>
#include <cstdint>

// Problem constants
#define T_STEPS 1024
#define BATCH   32
#define NHEAD   8
#define HSZ     128
#define G4      512            // 4*HS rows per head
#define NCOL    4096           // NH * 4 * HS
#define KDIM    1024           // input size (GEMM K)
#define MROWS   32768          // T*B

// ------------------------- device scratch ---------------------------------
__device__ float          g_linx[(size_t)T_STEPS * BATCH * NCOL];   // 512 MB
__device__ __nv_bfloat16  g_ah[(size_t)MROWS * KDIM];               // 64 MB
__device__ __nv_bfloat16  g_al[(size_t)MROWS * KDIM];               // 64 MB
__device__ __nv_bfloat16  g_bh[(size_t)NCOL * KDIM];                // 8 MB
__device__ __nv_bfloat16  g_bl[(size_t)NCOL * KDIM];                // 8 MB

// ------------------------- helpers ----------------------------------------
__device__ __forceinline__ uint32_t smem_u32(const void* p) {
    uint32_t a;
    asm("{ .reg .u64 t; cvta.to.shared.u64 t, %1; cvt.u32.u64 %0, t; }"
        : "=r"(a) : "l"(p));
    return a;
}
__device__ __forceinline__ void cpa16(uint32_t dst, const void* src) {
    asm volatile("cp.async.cg.shared.global [%0], [%1], 16;" :: "r"(dst), "l"(src));
}
#define CPA_COMMIT() asm volatile("cp.async.commit_group;" ::: "memory")

#define SWZ(o) ((o) ^ (((o) >> 3) & 0x70))

__device__ __forceinline__ void ldsm4(uint32_t addr, uint32_t& r0, uint32_t& r1,
                                      uint32_t& r2, uint32_t& r3) {
    asm volatile("ldmatrix.sync.aligned.m8n8.x4.shared.b16 {%0,%1,%2,%3}, [%4];"
                 : "=r"(r0), "=r"(r1), "=r"(r2), "=r"(r3) : "r"(addr));
}
__device__ __forceinline__ void mma16816(float* c, const uint32_t* a,
                                         uint32_t b0, uint32_t b1) {
    asm volatile("mma.sync.aligned.m16n8k16.row.col.f32.bf16.bf16.f32 "
                 "{%0,%1,%2,%3}, {%4,%5,%6,%7}, {%8,%9}, {%0,%1,%2,%3};"
                 : "+f"(c[0]), "+f"(c[1]), "+f"(c[2]), "+f"(c[3])
                 : "r"(a[0]), "r"(a[1]), "r"(a[2]), "r"(a[3]), "r"(b0), "r"(b1));
}

// ---------------- packed f32x2 helpers (recurrence) ------------------------
__device__ __forceinline__ unsigned long long pk(float lo, float hi) {
    unsigned long long r;
    asm("mov.b64 %0, {%1, %2};"
        : "=l"(r) : "r"(__float_as_uint(lo)), "r"(__float_as_uint(hi)));
    return r;
}
__device__ __forceinline__ void fma2(unsigned long long& d,
                                     unsigned long long a, unsigned long long b) {
    asm("fma.rn.f32x2 %0, %1, %2, %0;" : "+l"(d) : "l"(a), "l"(b));
}
__device__ __forceinline__ float2 upk(unsigned long long v) {
    unsigned int lo, hi;
    asm("mov.b64 {%0, %1}, %2;" : "=r"(lo), "=r"(hi) : "l"(v));
    return make_float2(__uint_as_float(lo), __uint_as_float(hi));
}

// ============================================================================
// Kernel 0: fp32 -> (bf16 hi, bf16 lo) split, 4 elems/thread
// ============================================================================
__global__ void split_bf16(const float* __restrict__ src,
                           __nv_bfloat16* __restrict__ hi,
                           __nv_bfloat16* __restrict__ lo, size_t n4) {
    size_t i = ((size_t)blockIdx.x * blockDim.x + threadIdx.x);
    if (i >= n4) return;
    i *= 4;
    const float4 v = *(const float4*)(src + i);
    __nv_bfloat16 h0 = __float2bfloat16(v.x), h1 = __float2bfloat16(v.y);
    __nv_bfloat16 h2 = __float2bfloat16(v.z), h3 = __float2bfloat16(v.w);
    __nv_bfloat16 l0 = __float2bfloat16(v.x - __bfloat162float(h0));
    __nv_bfloat16 l1 = __float2bfloat16(v.y - __bfloat162float(h1));
    __nv_bfloat16 l2 = __float2bfloat16(v.z - __bfloat162float(h2));
    __nv_bfloat16 l3 = __float2bfloat16(v.w - __bfloat162float(h3));
    ((__nv_bfloat162*)(hi + i))[0] = __nv_bfloat162(h0, h1);
    ((__nv_bfloat162*)(hi + i))[1] = __nv_bfloat162(h2, h3);
    ((__nv_bfloat162*)(lo + i))[0] = __nv_bfloat162(l0, l1);
    ((__nv_bfloat162*)(lo + i))[1] = __nv_bfloat162(l2, l3);
}

// ============================================================================
// Kernel 1: HMMA (mma.sync bf16) 3-split GEMM  C[M=32768, N=4096] fp32
//   C = Ah*Bh^T + Ah*Bl^T + Al*Bh^T,  A [M,K], B [N,K] both K-major bf16.
// CTA tile 128x128, BK=64, 8 warps (32x64 each), SW128 SMEM, ldmatrix.x4,
// 2-stage cp.async pipeline. 64 KB per stage, 128 KB total SMEM.
// ============================================================================
#define TKS   64
#define NKT   (KDIM / TKS)            // 16
#define SPL   16384                   // 128 rows * 128 B per split tile
#define STG   (4 * SPL)               // 64 KB per stage: [Ah][Al][Bh][Bl]
#define GEMM_SMEM (2 * STG)           // 128 KB

__global__ void __launch_bounds__(256, 1)
gemm3_hmma(const __nv_bfloat16* __restrict__ Ah, const __nv_bfloat16* __restrict__ Al,
           const __nv_bfloat16* __restrict__ Bh, const __nv_bfloat16* __restrict__ Bl,
           float* __restrict__ C) {
    extern __shared__ char smem[];
    const uint32_t usm = smem_u32(smem);
    const int t   = threadIdx.x;
    const int wid = t >> 5;
    const int lid = t & 31;
    const int wm  = wid >> 1;          // 0..3 -> rows wm*32
    const int wn  = wid & 1;           // 0..1 -> cols wn*64

    const size_t mrow0 = (size_t)blockIdx.y * 128;
    const size_t ncol0 = (size_t)blockIdx.x * 128;

    // ---- stage loader: 4096 x 16B chunks (A 2 splits + B 2 splits) --------
    auto load_stage = [&](int kt) {
        const uint32_t sb = usm + (uint32_t)((kt & 1) * STG);
        const size_t kof = (size_t)kt * TKS;
        #pragma unroll
        for (int i = 0; i < 4; ++i) {
            const int id  = (i << 8) + t;      // 0..1023
            const int row = id >> 3, c = id & 7;
            const uint32_t sw = SWZ((uint32_t)(row * 128 + c * 16));
            const size_t ga = (mrow0 + row) * KDIM + kof + c * 8;
            const size_t gb = (ncol0 + row) * KDIM + kof + c * 8;
            cpa16(sb + sw,           Ah + ga);
            cpa16(sb + SPL + sw,     Al + ga);
            cpa16(sb + 2 * SPL + sw, Bh + gb);
            cpa16(sb + 3 * SPL + sw, Bl + gb);
        }
        CPA_COMMIT();
    };

    load_stage(0);
    load_stage(1);

    // ---- per-lane ldmatrix addressing -------------------------------------
    const uint32_t xr  = (uint32_t)((lid & 7) << 4);   // swizzle XOR for this lane's row
    const uint32_t chi = (uint32_t)((lid >> 4) << 4);  // 0 or 16 bytes (k half)
    uint32_t arow[2], brow[4];
    #pragma unroll
    for (int mt = 0; mt < 2; ++mt)
        arow[mt] = (uint32_t)((wm * 32 + mt * 16 + (lid & 15)) * 128);
    #pragma unroll
    for (int nt = 0; nt < 4; ++nt)
        brow[nt] = (uint32_t)((wn * 64 + nt * 16 + (lid & 15)) * 128);

    float acc[2][8][4];
    #pragma unroll
    for (int mt = 0; mt < 2; ++mt)
        #pragma unroll
        for (int nn = 0; nn < 8; ++nn)
            #pragma unroll
            for (int q = 0; q < 4; ++q) acc[mt][nn][q] = 0.f;

    #pragma unroll 1
    for (int kt = 0; kt < NKT; ++kt) {
        if (kt == NKT - 1) asm volatile("cp.async.wait_group 0;" ::: "memory");
        else               asm volatile("cp.async.wait_group 1;" ::: "memory");
        __syncthreads();

        const uint32_t sb  = usm + (uint32_t)((kt & 1) * STG);
        const uint32_t sAh = sb, sAl = sb + SPL, sBh = sb + 2 * SPL, sBl = sb + 3 * SPL;

        #pragma unroll
        for (int ks = 0; ks < 4; ++ks) {
            const uint32_t cb = ((uint32_t)(ks * 32) + chi) ^ xr;

            uint32_t ahf[2][4], alf[2][4];
            #pragma unroll
            for (int mt = 0; mt < 2; ++mt) {
                ldsm4(sAh + arow[mt] + cb, ahf[mt][0], ahf[mt][1], ahf[mt][2], ahf[mt][3]);
                ldsm4(sAl + arow[mt] + cb, alf[mt][0], alf[mt][1], alf[mt][2], alf[mt][3]);
            }
            uint32_t bhf[4][4], blf[4][4];
            #pragma unroll
            for (int nt = 0; nt < 4; ++nt) {
                ldsm4(sBh + brow[nt] + cb, bhf[nt][0], bhf[nt][1], bhf[nt][2], bhf[nt][3]);
                ldsm4(sBl + brow[nt] + cb, blf[nt][0], blf[nt][1], blf[nt][2], blf[nt][3]);
            }
            #pragma unroll
            for (int mt = 0; mt < 2; ++mt) {
                #pragma unroll
                for (int nt = 0; nt < 4; ++nt) {
                    // Ah*Bh
                    mma16816(acc[mt][2 * nt],     ahf[mt], bhf[nt][0], bhf[nt][2]);
                    mma16816(acc[mt][2 * nt + 1], ahf[mt], bhf[nt][1], bhf[nt][3]);
                    // Ah*Bl
                    mma16816(acc[mt][2 * nt],     ahf[mt], blf[nt][0], blf[nt][2]);
                    mma16816(acc[mt][2 * nt + 1], ahf[mt], blf[nt][1], blf[nt][3]);
                    // Al*Bh
                    mma16816(acc[mt][2 * nt],     alf[mt], bhf[nt][0], bhf[nt][2]);
                    mma16816(acc[mt][2 * nt + 1], alf[mt], bhf[nt][1], bhf[nt][3]);
                }
            }
        }

        __syncthreads();
        if (kt + 2 < NKT) load_stage(kt + 2);
    }

    // ---- epilogue: fragment layout -> global fp32 --------------------------
    #pragma unroll
    for (int mt = 0; mt < 2; ++mt) {
        const size_t row = mrow0 + wm * 32 + mt * 16 + (lid >> 2);
        #pragma unroll
        for (int nt = 0; nt < 4; ++nt) {
            #pragma unroll
            for (int n8 = 0; n8 < 2; ++n8) {
                const float* cc = acc[mt][2 * nt + n8];
                const size_t col = ncol0 + wn * 64 + nt * 16 + n8 * 8 + (lid & 3) * 2;
                *(float2*)(C + row * NCOL + col)       = make_float2(cc[0], cc[1]);
                *(float2*)(C + (row + 8) * NCOL + col) = make_float2(cc[2], cc[3]);
            }
        }
    }
}

// ============================================================================
// Kernel 2: sequential sLSTM recurrence (cluster-2 per head-half), with
// lin_x register prefetch and out-store hidden in the cluster-barrier window.
// ============================================================================
__global__ void __launch_bounds__(256, 1) __cluster_dims__(2, 1, 1)
slstm_rec(const float* __restrict__ Whh,   // [NH, 512, 128]
          const float* __restrict__ bias,  // [NH, 512]
          const float* __restrict__ linx,  // [T, B, 4096]
          float* __restrict__ out) {       // [T, B, 1024]
    __shared__ __align__(16) float hsh[2][4][HSZ];
    __shared__ float gsh[4][4][64];

    const int bx   = blockIdx.x;
    const int half = bx & 1;
    const int pair = bx >> 1;
    const int head = pair & 7;
    const int bg   = pair >> 3;

    const int t  = threadIdx.x;
    const int g  = t >> 6;
    const int dr = t & 63;
    const int k  = g * HSZ + half * 64 + dr;

    const float4* wv = (const float4*)(Whh + ((size_t)head * G4 + k) * HSZ);
    unsigned long long wp[64];
    #pragma unroll
    for (int q = 0; q < 32; ++q) {
        const float4 v = wv[q];
        wp[2 * q]     = pk(v.x, v.y);
        wp[2 * q + 1] = pk(v.z, v.w);
    }
    const float bk = bias[head * G4 + k];

    const int b2     = t >> 6;
    const int d      = t & 63;
    const int j      = half * 64 + d;
    const int bglob  = bg * 4 + b2;
    const int outcol = head * HSZ + j;

    for (int z = t; z < 2 * 4 * HSZ; z += 256) ((float*)hsh)[z] = 0.f;

    unsigned int lbase = (unsigned int)__cvta_generic_to_shared(&hsh[0][0][0]);
    unsigned int rbase;
    const unsigned int peer = (unsigned int)(half ^ 1);
    asm("mapa.shared::cluster.u32 %0, %1, %2;" : "=r"(rbase) : "r"(lbase), "r"(peer));

    float c_ = 0.f, m_ = 0.f, n_ = 0.f;

    asm volatile("barrier.cluster.arrive.aligned;" ::: "memory");
    asm volatile("barrier.cluster.wait.aligned;" ::: "memory");

    int cur = 0;
    const float* lxbase = linx + (size_t)(bg * 4) * NCOL + (size_t)head * G4 + k;
    const size_t lxstep = (size_t)BATCH * NCOL;

    // prologue prefetch: step 0
    float lx0 = __ldg(lxbase), lx1 = __ldg(lxbase + NCOL);
    float lx2 = __ldg(lxbase + 2 * NCOL), lx3 = __ldg(lxbase + 3 * NCOL);

    #pragma unroll 1
    for (int ts = 0; ts < T_STEPS; ++ts) {
        unsigned long long a0 = 0ull, a1 = 0ull, a2 = 0ull, a3 = 0ull;
        #pragma unroll
        for (int q4 = 0; q4 < 32; ++q4) {
            const ulonglong2 h0 = *(const ulonglong2*)&hsh[cur][0][q4 * 4];
            fma2(a0, wp[2 * q4], h0.x); fma2(a0, wp[2 * q4 + 1], h0.y);
            const ulonglong2 h1 = *(const ulonglong2*)&hsh[cur][1][q4 * 4];
            fma2(a1, wp[2 * q4], h1.x); fma2(a1, wp[2 * q4 + 1], h1.y);
            const ulonglong2 h2 = *(const ulonglong2*)&hsh[cur][2][q4 * 4];
            fma2(a2, wp[2 * q4], h2.x); fma2(a2, wp[2 * q4 + 1], h2.y);
            const ulonglong2 h3 = *(const ulonglong2*)&hsh[cur][3][q4 * 4];
            fma2(a3, wp[2 * q4], h3.x); fma2(a3, wp[2 * q4 + 1], h3.y);
        }
        const float2 s0 = upk(a0), s1 = upk(a1), s2 = upk(a2), s3 = upk(a3);
        gsh[g][0][dr] = s0.x + s0.y + lx0 + bk;
        gsh[g][1][dr] = s1.x + s1.y + lx1 + bk;
        gsh[g][2][dr] = s2.x + s2.y + lx2 + bk;
        gsh[g][3][dr] = s3.x + s3.y + lx3 + bk;
        __syncthreads();

        const float iv = gsh[0][b2][d];
        const float fv = gsh[1][b2][d];
        const float zv = gsh[2][b2][d];
        const float ov = gsh[3][b2][d];

        const float zt = 1.f - 2.f / (__expf(2.f * zv) + 1.f);   // tanh
        const float os = 1.f / (1.f + __expf(-ov));              // sigmoid
        const float fm = fv + m_;
        const float mn = fmaxf(fm, iv);
        const float ie = __expf(iv - mn);
        const float fe = __expf(fm - mn);
        c_ = fe * c_ + ie * zt;
        n_ = fe * n_ + ie;
        m_ = mn;
        const float h = os * (c_ / n_);

        const int nxt = cur ^ 1;
        hsh[nxt][b2][j] = h;
        const unsigned int roff =
            ((unsigned int)((nxt * 4 + b2) * HSZ + j)) * 4u;
        asm volatile("st.shared::cluster.f32 [%0], %1;"
                     :: "r"(rbase + roff), "f"(h) : "memory");

        asm volatile("barrier.cluster.arrive.aligned;" ::: "memory");

        // hide gmem traffic in the barrier window
        out[((size_t)ts * BATCH + bglob) * (NHEAD * HSZ) + outcol] = h;
        const int tn = (ts + 1 < T_STEPS) ? ts + 1 : ts;
        const float* lpn = lxbase + (size_t)tn * lxstep;
        lx0 = __ldg(lpn);            lx1 = __ldg(lpn + NCOL);
        lx2 = __ldg(lpn + 2 * NCOL); lx3 = __ldg(lpn + 3 * NCOL);

        asm volatile("barrier.cluster.wait.aligned;" ::: "memory");
        cur = nxt;
    }
}

// ============================================================================
extern "C" void kernel_launch(void* const* d_in, const int* in_sizes, int n_in,
                              void* d_out, int out_size) {
    const float* xs   = (const float*)d_in[0];  // [T, B, I]
    const float* wih  = (const float*)d_in[1];  // [NH, 4*HS, I]
    const float* whh  = (const float*)d_in[2];  // [NH, 4*HS, HS]
    const float* bias = (const float*)d_in[3];  // [NH, 4*HS]
    float* out = (float*)d_out;                 // [T, B, H]

    float *linx; __nv_bfloat16 *ah, *al, *bh, *bl;
    cudaGetSymbolAddress((void**)&linx, g_linx);
    cudaGetSymbolAddress((void**)&ah, g_ah);
    cudaGetSymbolAddress((void**)&al, g_al);
    cudaGetSymbolAddress((void**)&bh, g_bh);
    cudaGetSymbolAddress((void**)&bl, g_bl);

    cudaFuncSetAttribute(gemm3_hmma, cudaFuncAttributeMaxDynamicSharedMemorySize,
                         GEMM_SMEM);

    const size_t nA4 = (size_t)MROWS * KDIM / 4;
    const size_t nB4 = (size_t)NCOL * KDIM / 4;
    split_bf16<<<(unsigned)((nA4 + 255) / 256), 256>>>(xs, ah, al, nA4);
    split_bf16<<<(unsigned)((nB4 + 255) / 256), 256>>>(wih, bh, bl, nB4);

    dim3 gg(NCOL / 128, MROWS / 128);              // (32, 256)
    gemm3_hmma<<<gg, 256, GEMM_SMEM>>>(ah, al, bh, bl, linx);

    slstm_rec<<<128, 256>>>(whh, bias, linx, out);
}

// round 7
// speedup vs baseline: 1.8479x; 1.0051x over previous
#include <cuda_runtime.h>
#include <cuda_bf16.h>
#include <cstdint>

// Problem constants
#define T_STEPS 1024
#define BATCH   32
#define NHEAD   8
#define HSZ     128
#define G4      512            // 4*HS rows per head
#define NCOL    4096           // NH * 4 * HS
#define KDIM    1024           // input size (GEMM K)
#define MROWS   32768          // T*B

// ------------------------- device scratch ---------------------------------
__device__ float          g_linx[(size_t)T_STEPS * BATCH * NCOL];   // 512 MB
__device__ __nv_bfloat16  g_ah[(size_t)MROWS * KDIM];               // 64 MB
__device__ __nv_bfloat16  g_al[(size_t)MROWS * KDIM];               // 64 MB
__device__ __nv_bfloat16  g_bh[(size_t)NCOL * KDIM];                // 8 MB
__device__ __nv_bfloat16  g_bl[(size_t)NCOL * KDIM];                // 8 MB

// ------------------------- helpers ----------------------------------------
__device__ __forceinline__ uint32_t smem_u32(const void* p) {
    uint32_t a;
    asm("{ .reg .u64 t; cvta.to.shared.u64 t, %1; cvt.u32.u64 %0, t; }"
        : "=r"(a) : "l"(p));
    return a;
}
__device__ __forceinline__ void cpa16(uint32_t dst, const void* src) {
    asm volatile("cp.async.cg.shared.global [%0], [%1], 16;" :: "r"(dst), "l"(src));
}
#define CPA_COMMIT() asm volatile("cp.async.commit_group;" ::: "memory")

#define SWZ(o) ((o) ^ (((o) >> 3) & 0x70))

__device__ __forceinline__ void ldsm4(uint32_t addr, uint32_t& r0, uint32_t& r1,
                                      uint32_t& r2, uint32_t& r3) {
    asm volatile("ldmatrix.sync.aligned.m8n8.x4.shared.b16 {%0,%1,%2,%3}, [%4];"
                 : "=r"(r0), "=r"(r1), "=r"(r2), "=r"(r3) : "r"(addr));
}
__device__ __forceinline__ void mma16816(float* c, const uint32_t* a,
                                         uint32_t b0, uint32_t b1) {
    asm volatile("mma.sync.aligned.m16n8k16.row.col.f32.bf16.bf16.f32 "
                 "{%0,%1,%2,%3}, {%4,%5,%6,%7}, {%8,%9}, {%0,%1,%2,%3};"
                 : "+f"(c[0]), "+f"(c[1]), "+f"(c[2]), "+f"(c[3])
                 : "r"(a[0]), "r"(a[1]), "r"(a[2]), "r"(a[3]), "r"(b0), "r"(b1));
}

// ---------------- packed f32x2 helpers (recurrence) ------------------------
__device__ __forceinline__ unsigned long long pk(float lo, float hi) {
    unsigned long long r;
    asm("mov.b64 %0, {%1, %2};"
        : "=l"(r) : "r"(__float_as_uint(lo)), "r"(__float_as_uint(hi)));
    return r;
}
__device__ __forceinline__ void fma2(unsigned long long& d,
                                     unsigned long long a, unsigned long long b) {
    asm("fma.rn.f32x2 %0, %1, %2, %0;" : "+l"(d) : "l"(a), "l"(b));
}
__device__ __forceinline__ float2 upk(unsigned long long v) {
    unsigned int lo, hi;
    asm("mov.b64 {%0, %1}, %2;" : "=r"(lo), "=r"(hi) : "l"(v));
    return make_float2(__uint_as_float(lo), __uint_as_float(hi));
}

// ============================================================================
// Kernel 0: fp32 -> (bf16 hi, bf16 lo) split, 4 elems/thread
// ============================================================================
__global__ void split_bf16(const float* __restrict__ src,
                           __nv_bfloat16* __restrict__ hi,
                           __nv_bfloat16* __restrict__ lo, size_t n4) {
    size_t i = ((size_t)blockIdx.x * blockDim.x + threadIdx.x);
    if (i >= n4) return;
    i *= 4;
    const float4 v = *(const float4*)(src + i);
    __nv_bfloat16 h0 = __float2bfloat16(v.x), h1 = __float2bfloat16(v.y);
    __nv_bfloat16 h2 = __float2bfloat16(v.z), h3 = __float2bfloat16(v.w);
    __nv_bfloat16 l0 = __float2bfloat16(v.x - __bfloat162float(h0));
    __nv_bfloat16 l1 = __float2bfloat16(v.y - __bfloat162float(h1));
    __nv_bfloat16 l2 = __float2bfloat16(v.z - __bfloat162float(h2));
    __nv_bfloat16 l3 = __float2bfloat16(v.w - __bfloat162float(h3));
    ((__nv_bfloat162*)(hi + i))[0] = __nv_bfloat162(h0, h1);
    ((__nv_bfloat162*)(hi + i))[1] = __nv_bfloat162(h2, h3);
    ((__nv_bfloat162*)(lo + i))[0] = __nv_bfloat162(l0, l1);
    ((__nv_bfloat162*)(lo + i))[1] = __nv_bfloat162(l2, l3);
}

// ============================================================================
// Kernel 1: HMMA (mma.sync bf16) 3-split GEMM  C[M=32768, N=4096] fp32
//   C = Ah*Bh^T + Ah*Bl^T + Al*Bh^T,  A [M,K], B [N,K] both K-major bf16.
// CTA tile 128x128, BK=64, 8 warps (32x64 each), SW128 SMEM, ldmatrix.x4,
// 2-stage cp.async pipeline. 64 KB per stage, 128 KB total SMEM.
// ============================================================================
#define TKS   64
#define NKT   (KDIM / TKS)            // 16
#define SPL   16384                   // 128 rows * 128 B per split tile
#define STG   (4 * SPL)               // 64 KB per stage: [Ah][Al][Bh][Bl]
#define GEMM_SMEM (2 * STG)           // 128 KB

__global__ void __launch_bounds__(256, 1)
gemm3_hmma(const __nv_bfloat16* __restrict__ Ah, const __nv_bfloat16* __restrict__ Al,
           const __nv_bfloat16* __restrict__ Bh, const __nv_bfloat16* __restrict__ Bl,
           float* __restrict__ C) {
    extern __shared__ char smem[];
    const uint32_t usm = smem_u32(smem);
    const int t   = threadIdx.x;
    const int wid = t >> 5;
    const int lid = t & 31;
    const int wm  = wid >> 1;          // 0..3 -> rows wm*32
    const int wn  = wid & 1;           // 0..1 -> cols wn*64

    const size_t mrow0 = (size_t)blockIdx.y * 128;
    const size_t ncol0 = (size_t)blockIdx.x * 128;

    // ---- stage loader: 4096 x 16B chunks (A 2 splits + B 2 splits) --------
    auto load_stage = [&](int kt) {
        const uint32_t sb = usm + (uint32_t)((kt & 1) * STG);
        const size_t kof = (size_t)kt * TKS;
        #pragma unroll
        for (int i = 0; i < 4; ++i) {
            const int id  = (i << 8) + t;      // 0..1023
            const int row = id >> 3, c = id & 7;
            const uint32_t sw = SWZ((uint32_t)(row * 128 + c * 16));
            const size_t ga = (mrow0 + row) * KDIM + kof + c * 8;
            const size_t gb = (ncol0 + row) * KDIM + kof + c * 8;
            cpa16(sb + sw,           Ah + ga);
            cpa16(sb + SPL + sw,     Al + ga);
            cpa16(sb + 2 * SPL + sw, Bh + gb);
            cpa16(sb + 3 * SPL + sw, Bl + gb);
        }
        CPA_COMMIT();
    };

    load_stage(0);
    load_stage(1);

    // ---- per-lane ldmatrix addressing -------------------------------------
    const uint32_t xr  = (uint32_t)((lid & 7) << 4);   // swizzle XOR for this lane's row
    const uint32_t chi = (uint32_t)((lid >> 4) << 4);  // 0 or 16 bytes (k half)
    uint32_t arow[2], brow[4];
    #pragma unroll
    for (int mt = 0; mt < 2; ++mt)
        arow[mt] = (uint32_t)((wm * 32 + mt * 16 + (lid & 15)) * 128);
    #pragma unroll
    for (int nt = 0; nt < 4; ++nt)
        brow[nt] = (uint32_t)((wn * 64 + nt * 16 + (lid & 15)) * 128);

    float acc[2][8][4];
    #pragma unroll
    for (int mt = 0; mt < 2; ++mt)
        #pragma unroll
        for (int nn = 0; nn < 8; ++nn)
            #pragma unroll
            for (int q = 0; q < 4; ++q) acc[mt][nn][q] = 0.f;

    #pragma unroll 1
    for (int kt = 0; kt < NKT; ++kt) {
        if (kt == NKT - 1) asm volatile("cp.async.wait_group 0;" ::: "memory");
        else               asm volatile("cp.async.wait_group 1;" ::: "memory");
        __syncthreads();

        const uint32_t sb  = usm + (uint32_t)((kt & 1) * STG);
        const uint32_t sAh = sb, sAl = sb + SPL, sBh = sb + 2 * SPL, sBl = sb + 3 * SPL;

        #pragma unroll
        for (int ks = 0; ks < 4; ++ks) {
            const uint32_t cb = ((uint32_t)(ks * 32) + chi) ^ xr;

            uint32_t ahf[2][4], alf[2][4];
            #pragma unroll
            for (int mt = 0; mt < 2; ++mt) {
                ldsm4(sAh + arow[mt] + cb, ahf[mt][0], ahf[mt][1], ahf[mt][2], ahf[mt][3]);
                ldsm4(sAl + arow[mt] + cb, alf[mt][0], alf[mt][1], alf[mt][2], alf[mt][3]);
            }
            uint32_t bhf[4][4], blf[4][4];
            #pragma unroll
            for (int nt = 0; nt < 4; ++nt) {
                ldsm4(sBh + brow[nt] + cb, bhf[nt][0], bhf[nt][1], bhf[nt][2], bhf[nt][3]);
                ldsm4(sBl + brow[nt] + cb, blf[nt][0], blf[nt][1], blf[nt][2], blf[nt][3]);
            }
            #pragma unroll
            for (int mt = 0; mt < 2; ++mt) {
                #pragma unroll
                for (int nt = 0; nt < 4; ++nt) {
                    // Ah*Bh
                    mma16816(acc[mt][2 * nt],     ahf[mt], bhf[nt][0], bhf[nt][2]);
                    mma16816(acc[mt][2 * nt + 1], ahf[mt], bhf[nt][1], bhf[nt][3]);
                    // Ah*Bl
                    mma16816(acc[mt][2 * nt],     ahf[mt], blf[nt][0], blf[nt][2]);
                    mma16816(acc[mt][2 * nt + 1], ahf[mt], blf[nt][1], blf[nt][3]);
                    // Al*Bh
                    mma16816(acc[mt][2 * nt],     alf[mt], bhf[nt][0], bhf[nt][2]);
                    mma16816(acc[mt][2 * nt + 1], alf[mt], bhf[nt][1], bhf[nt][3]);
                }
            }
        }

        __syncthreads();
        if (kt + 2 < NKT) load_stage(kt + 2);
    }

    // ---- epilogue: fragment layout -> global fp32 --------------------------
    #pragma unroll
    for (int mt = 0; mt < 2; ++mt) {
        const size_t row = mrow0 + wm * 32 + mt * 16 + (lid >> 2);
        #pragma unroll
        for (int nt = 0; nt < 4; ++nt) {
            #pragma unroll
            for (int n8 = 0; n8 < 2; ++n8) {
                const float* cc = acc[mt][2 * nt + n8];
                const size_t col = ncol0 + wn * 64 + nt * 16 + n8 * 8 + (lid & 3) * 2;
                *(float2*)(C + row * NCOL + col)       = make_float2(cc[0], cc[1]);
                *(float2*)(C + (row + 8) * NCOL + col) = make_float2(cc[2], cc[3]);
            }
        }
    }
}

// ============================================================================
// Kernel 2: sequential sLSTM recurrence (cluster-2 per head-half), with
// lin_x register prefetch and out-store hidden in the cluster-barrier window.
// ============================================================================
__global__ void __launch_bounds__(256, 1) __cluster_dims__(2, 1, 1)
slstm_rec(const float* __restrict__ Whh,   // [NH, 512, 128]
          const float* __restrict__ bias,  // [NH, 512]
          const float* __restrict__ linx,  // [T, B, 4096]
          float* __restrict__ out) {       // [T, B, 1024]
    __shared__ __align__(16) float hsh[2][4][HSZ];
    __shared__ float gsh[4][4][64];

    const int bx   = blockIdx.x;
    const int half = bx & 1;
    const int pair = bx >> 1;
    const int head = pair & 7;
    const int bg   = pair >> 3;

    const int t  = threadIdx.x;
    const int g  = t >> 6;
    const int dr = t & 63;
    const int k  = g * HSZ + half * 64 + dr;

    const float4* wv = (const float4*)(Whh + ((size_t)head * G4 + k) * HSZ);
    unsigned long long wp[64];
    #pragma unroll
    for (int q = 0; q < 32; ++q) {
        const float4 v = wv[q];
        wp[2 * q]     = pk(v.x, v.y);
        wp[2 * q + 1] = pk(v.z, v.w);
    }
    const float bk = bias[head * G4 + k];

    const int b2     = t >> 6;
    const int d      = t & 63;
    const int j      = half * 64 + d;
    const int bglob  = bg * 4 + b2;
    const int outcol = head * HSZ + j;

    for (int z = t; z < 2 * 4 * HSZ; z += 256) ((float*)hsh)[z] = 0.f;

    unsigned int lbase = (unsigned int)__cvta_generic_to_shared(&hsh[0][0][0]);
    unsigned int rbase;
    const unsigned int peer = (unsigned int)(half ^ 1);
    asm("mapa.shared::cluster.u32 %0, %1, %2;" : "=r"(rbase) : "r"(lbase), "r"(peer));

    float c_ = 0.f, m_ = 0.f, n_ = 0.f;

    asm volatile("barrier.cluster.arrive.aligned;" ::: "memory");
    asm volatile("barrier.cluster.wait.aligned;" ::: "memory");

    int cur = 0;
    const float* lxbase = linx + (size_t)(bg * 4) * NCOL + (size_t)head * G4 + k;
    const size_t lxstep = (size_t)BATCH * NCOL;

    // prologue prefetch: step 0
    float lx0 = __ldg(lxbase), lx1 = __ldg(lxbase + NCOL);
    float lx2 = __ldg(lxbase + 2 * NCOL), lx3 = __ldg(lxbase + 3 * NCOL);

    #pragma unroll 1
    for (int ts = 0; ts < T_STEPS; ++ts) {
        unsigned long long a0 = 0ull, a1 = 0ull, a2 = 0ull, a3 = 0ull;
        #pragma unroll
        for (int q4 = 0; q4 < 32; ++q4) {
            const ulonglong2 h0 = *(const ulonglong2*)&hsh[cur][0][q4 * 4];
            fma2(a0, wp[2 * q4], h0.x); fma2(a0, wp[2 * q4 + 1], h0.y);
            const ulonglong2 h1 = *(const ulonglong2*)&hsh[cur][1][q4 * 4];
            fma2(a1, wp[2 * q4], h1.x); fma2(a1, wp[2 * q4 + 1], h1.y);
            const ulonglong2 h2 = *(const ulonglong2*)&hsh[cur][2][q4 * 4];
            fma2(a2, wp[2 * q4], h2.x); fma2(a2, wp[2 * q4 + 1], h2.y);
            const ulonglong2 h3 = *(const ulonglong2*)&hsh[cur][3][q4 * 4];
            fma2(a3, wp[2 * q4], h3.x); fma2(a3, wp[2 * q4 + 1], h3.y);
        }
        const float2 s0 = upk(a0), s1 = upk(a1), s2 = upk(a2), s3 = upk(a3);
        gsh[g][0][dr] = s0.x + s0.y + lx0 + bk;
        gsh[g][1][dr] = s1.x + s1.y + lx1 + bk;
        gsh[g][2][dr] = s2.x + s2.y + lx2 + bk;
        gsh[g][3][dr] = s3.x + s3.y + lx3 + bk;
        __syncthreads();

        const float iv = gsh[0][b2][d];
        const float fv = gsh[1][b2][d];
        const float zv = gsh[2][b2][d];
        const float ov = gsh[3][b2][d];

        const float zt = 1.f - 2.f / (__expf(2.f * zv) + 1.f);   // tanh
        const float os = 1.f / (1.f + __expf(-ov));              // sigmoid
        const float fm = fv + m_;
        const float mn = fmaxf(fm, iv);
        const float ie = __expf(iv - mn);
        const float fe = __expf(fm - mn);
        c_ = fe * c_ + ie * zt;
        n_ = fe * n_ + ie;
        m_ = mn;
        const float h = os * (c_ / n_);

        const int nxt = cur ^ 1;
        hsh[nxt][b2][j] = h;
        const unsigned int roff =
            ((unsigned int)((nxt * 4 + b2) * HSZ + j)) * 4u;
        asm volatile("st.shared::cluster.f32 [%0], %1;"
                     :: "r"(rbase + roff), "f"(h) : "memory");

        asm volatile("barrier.cluster.arrive.aligned;" ::: "memory");

        // hide gmem traffic in the barrier window
        out[((size_t)ts * BATCH + bglob) * (NHEAD * HSZ) + outcol] = h;
        const int tn = (ts + 1 < T_STEPS) ? ts + 1 : ts;
        const float* lpn = lxbase + (size_t)tn * lxstep;
        lx0 = __ldg(lpn);            lx1 = __ldg(lpn + NCOL);
        lx2 = __ldg(lpn + 2 * NCOL); lx3 = __ldg(lpn + 3 * NCOL);

        asm volatile("barrier.cluster.wait.aligned;" ::: "memory");
        cur = nxt;
    }
}

// ============================================================================
extern "C" void kernel_launch(void* const* d_in, const int* in_sizes, int n_in,
                              void* d_out, int out_size) {
    const float* xs   = (const float*)d_in[0];  // [T, B, I]
    const float* wih  = (const float*)d_in[1];  // [NH, 4*HS, I]
    const float* whh  = (const float*)d_in[2];  // [NH, 4*HS, HS]
    const float* bias = (const float*)d_in[3];  // [NH, 4*HS]
    float* out = (float*)d_out;                 // [T, B, H]

    float *linx; __nv_bfloat16 *ah, *al, *bh, *bl;
    cudaGetSymbolAddress((void**)&linx, g_linx);
    cudaGetSymbolAddress((void**)&ah, g_ah);
    cudaGetSymbolAddress((void**)&al, g_al);
    cudaGetSymbolAddress((void**)&bh, g_bh);
    cudaGetSymbolAddress((void**)&bl, g_bl);

    cudaFuncSetAttribute(gemm3_hmma, cudaFuncAttributeMaxDynamicSharedMemorySize,
                         GEMM_SMEM);

    const size_t nA4 = (size_t)MROWS * KDIM / 4;
    const size_t nB4 = (size_t)NCOL * KDIM / 4;
    split_bf16<<<(unsigned)((nA4 + 255) / 256), 256>>>(xs, ah, al, nA4);
    split_bf16<<<(unsigned)((nB4 + 255) / 256), 256>>>(wih, bh, bl, nB4);

    dim3 gg(NCOL / 128, MROWS / 128);              // (32, 256)
    gemm3_hmma<<<gg, 256, GEMM_SMEM>>>(ah, al, bh, bl, linx);

    slstm_rec<<<128, 256>>>(whh, bias, linx, out);
}

// round 8
// speedup vs baseline: 1.8484x; 1.0003x over previous
#include <cuda_runtime.h>
#include <cuda_bf16.h>
#include <cstdint>

// Problem constants
#define T_STEPS 1024
#define BATCH   32
#define NHEAD   8
#define HSZ     128
#define G4      512            // 4*HS rows per head
#define NCOL    4096           // NH * 4 * HS
#define KDIM    1024           // input size (GEMM K)
#define MROWS   32768          // T*B

// ------------------------- device scratch ---------------------------------
__device__ float          g_linx[(size_t)T_STEPS * BATCH * NCOL];   // 512 MB
__device__ __nv_bfloat16  g_ah[(size_t)MROWS * KDIM];               // 64 MB
__device__ __nv_bfloat16  g_al[(size_t)MROWS * KDIM];               // 64 MB
__device__ __nv_bfloat16  g_bh[(size_t)NCOL * KDIM];                // 8 MB
__device__ __nv_bfloat16  g_bl[(size_t)NCOL * KDIM];                // 8 MB

// ------------------------- helpers ----------------------------------------
__device__ __forceinline__ uint32_t smem_u32(const void* p) {
    uint32_t a;
    asm("{ .reg .u64 t; cvta.to.shared.u64 t, %1; cvt.u32.u64 %0, t; }"
        : "=r"(a) : "l"(p));
    return a;
}
__device__ __forceinline__ void cpa16(uint32_t dst, const void* src) {
    asm volatile("cp.async.cg.shared.global [%0], [%1], 16;" :: "r"(dst), "l"(src));
}
#define CPA_COMMIT() asm volatile("cp.async.commit_group;" ::: "memory")

#define SWZ(o) ((o) ^ (((o) >> 3) & 0x70))

__device__ __forceinline__ void ldsm4(uint32_t addr, uint32_t& r0, uint32_t& r1,
                                      uint32_t& r2, uint32_t& r3) {
    asm volatile("ldmatrix.sync.aligned.m8n8.x4.shared.b16 {%0,%1,%2,%3}, [%4];"
                 : "=r"(r0), "=r"(r1), "=r"(r2), "=r"(r3) : "r"(addr));
}
__device__ __forceinline__ void mma16816(float* c, const uint32_t* a,
                                         uint32_t b0, uint32_t b1) {
    asm volatile("mma.sync.aligned.m16n8k16.row.col.f32.bf16.bf16.f32 "
                 "{%0,%1,%2,%3}, {%4,%5,%6,%7}, {%8,%9}, {%0,%1,%2,%3};"
                 : "+f"(c[0]), "+f"(c[1]), "+f"(c[2]), "+f"(c[3])
                 : "r"(a[0]), "r"(a[1]), "r"(a[2]), "r"(a[3]), "r"(b0), "r"(b1));
}

// ---------------- packed f32x2 helpers (recurrence) ------------------------
__device__ __forceinline__ unsigned long long pk(float lo, float hi) {
    unsigned long long r;
    asm("mov.b64 %0, {%1, %2};"
        : "=l"(r) : "r"(__float_as_uint(lo)), "r"(__float_as_uint(hi)));
    return r;
}
__device__ __forceinline__ void fma2(unsigned long long& d,
                                     unsigned long long a, unsigned long long b) {
    asm("fma.rn.f32x2 %0, %1, %2, %0;" : "+l"(d) : "l"(a), "l"(b));
}
__device__ __forceinline__ float2 upk(unsigned long long v) {
    unsigned int lo, hi;
    asm("mov.b64 {%0, %1}, %2;" : "=r"(lo), "=r"(hi) : "l"(v));
    return make_float2(__uint_as_float(lo), __uint_as_float(hi));
}

// ============================================================================
// Kernel 0: fp32 -> (bf16 hi, bf16 lo) split, 4 elems/thread
// ============================================================================
__global__ void split_bf16(const float* __restrict__ src,
                           __nv_bfloat16* __restrict__ hi,
                           __nv_bfloat16* __restrict__ lo, size_t n4) {
    size_t i = ((size_t)blockIdx.x * blockDim.x + threadIdx.x);
    if (i >= n4) return;
    i *= 4;
    const float4 v = *(const float4*)(src + i);
    __nv_bfloat16 h0 = __float2bfloat16(v.x), h1 = __float2bfloat16(v.y);
    __nv_bfloat16 h2 = __float2bfloat16(v.z), h3 = __float2bfloat16(v.w);
    __nv_bfloat16 l0 = __float2bfloat16(v.x - __bfloat162float(h0));
    __nv_bfloat16 l1 = __float2bfloat16(v.y - __bfloat162float(h1));
    __nv_bfloat16 l2 = __float2bfloat16(v.z - __bfloat162float(h2));
    __nv_bfloat16 l3 = __float2bfloat16(v.w - __bfloat162float(h3));
    ((__nv_bfloat162*)(hi + i))[0] = __nv_bfloat162(h0, h1);
    ((__nv_bfloat162*)(hi + i))[1] = __nv_bfloat162(h2, h3);
    ((__nv_bfloat162*)(lo + i))[0] = __nv_bfloat162(l0, l1);
    ((__nv_bfloat162*)(lo + i))[1] = __nv_bfloat162(l2, l3);
}

// ============================================================================
// Kernel 1: HMMA (mma.sync bf16) 3-split GEMM  C[M=32768, N=4096] fp32
//   C = Ah*Bh^T + Ah*Bl^T + Al*Bh^T,  A [M,K], B [N,K] both K-major bf16.
// CTA tile 128x128, BK=64, 8 warps (32x64 each), SW128 SMEM, ldmatrix.x4,
// 2-stage cp.async pipeline. 64 KB per stage, 128 KB total SMEM.
// ============================================================================
#define TKS   64
#define NKT   (KDIM / TKS)            // 16
#define SPL   16384                   // 128 rows * 128 B per split tile
#define STG   (4 * SPL)               // 64 KB per stage: [Ah][Al][Bh][Bl]
#define GEMM_SMEM (2 * STG)           // 128 KB

__global__ void __launch_bounds__(256, 1)
gemm3_hmma(const __nv_bfloat16* __restrict__ Ah, const __nv_bfloat16* __restrict__ Al,
           const __nv_bfloat16* __restrict__ Bh, const __nv_bfloat16* __restrict__ Bl,
           float* __restrict__ C) {
    extern __shared__ char smem[];
    const uint32_t usm = smem_u32(smem);
    const int t   = threadIdx.x;
    const int wid = t >> 5;
    const int lid = t & 31;
    const int wm  = wid >> 1;          // 0..3 -> rows wm*32
    const int wn  = wid & 1;           // 0..1 -> cols wn*64

    const size_t mrow0 = (size_t)blockIdx.y * 128;
    const size_t ncol0 = (size_t)blockIdx.x * 128;

    // ---- stage loader: 4096 x 16B chunks (A 2 splits + B 2 splits) --------
    auto load_stage = [&](int kt) {
        const uint32_t sb = usm + (uint32_t)((kt & 1) * STG);
        const size_t kof = (size_t)kt * TKS;
        #pragma unroll
        for (int i = 0; i < 4; ++i) {
            const int id  = (i << 8) + t;      // 0..1023
            const int row = id >> 3, c = id & 7;
            const uint32_t sw = SWZ((uint32_t)(row * 128 + c * 16));
            const size_t ga = (mrow0 + row) * KDIM + kof + c * 8;
            const size_t gb = (ncol0 + row) * KDIM + kof + c * 8;
            cpa16(sb + sw,           Ah + ga);
            cpa16(sb + SPL + sw,     Al + ga);
            cpa16(sb + 2 * SPL + sw, Bh + gb);
            cpa16(sb + 3 * SPL + sw, Bl + gb);
        }
        CPA_COMMIT();
    };

    load_stage(0);
    load_stage(1);

    // ---- per-lane ldmatrix addressing -------------------------------------
    const uint32_t xr  = (uint32_t)((lid & 7) << 4);   // swizzle XOR for this lane's row
    const uint32_t chi = (uint32_t)((lid >> 4) << 4);  // 0 or 16 bytes (k half)
    uint32_t arow[2], brow[4];
    #pragma unroll
    for (int mt = 0; mt < 2; ++mt)
        arow[mt] = (uint32_t)((wm * 32 + mt * 16 + (lid & 15)) * 128);
    #pragma unroll
    for (int nt = 0; nt < 4; ++nt)
        brow[nt] = (uint32_t)((wn * 64 + nt * 16 + (lid & 15)) * 128);

    float acc[2][8][4];
    #pragma unroll
    for (int mt = 0; mt < 2; ++mt)
        #pragma unroll
        for (int nn = 0; nn < 8; ++nn)
            #pragma unroll
            for (int q = 0; q < 4; ++q) acc[mt][nn][q] = 0.f;

    #pragma unroll 1
    for (int kt = 0; kt < NKT; ++kt) {
        if (kt == NKT - 1) asm volatile("cp.async.wait_group 0;" ::: "memory");
        else               asm volatile("cp.async.wait_group 1;" ::: "memory");
        __syncthreads();

        const uint32_t sb  = usm + (uint32_t)((kt & 1) * STG);
        const uint32_t sAh = sb, sAl = sb + SPL, sBh = sb + 2 * SPL, sBl = sb + 3 * SPL;

        #pragma unroll
        for (int ks = 0; ks < 4; ++ks) {
            const uint32_t cb = ((uint32_t)(ks * 32) + chi) ^ xr;

            uint32_t ahf[2][4], alf[2][4];
            #pragma unroll
            for (int mt = 0; mt < 2; ++mt) {
                ldsm4(sAh + arow[mt] + cb, ahf[mt][0], ahf[mt][1], ahf[mt][2], ahf[mt][3]);
                ldsm4(sAl + arow[mt] + cb, alf[mt][0], alf[mt][1], alf[mt][2], alf[mt][3]);
            }
            uint32_t bhf[4][4], blf[4][4];
            #pragma unroll
            for (int nt = 0; nt < 4; ++nt) {
                ldsm4(sBh + brow[nt] + cb, bhf[nt][0], bhf[nt][1], bhf[nt][2], bhf[nt][3]);
                ldsm4(sBl + brow[nt] + cb, blf[nt][0], blf[nt][1], blf[nt][2], blf[nt][3]);
            }
            #pragma unroll
            for (int mt = 0; mt < 2; ++mt) {
                #pragma unroll
                for (int nt = 0; nt < 4; ++nt) {
                    // Ah*Bh
                    mma16816(acc[mt][2 * nt],     ahf[mt], bhf[nt][0], bhf[nt][2]);
                    mma16816(acc[mt][2 * nt + 1], ahf[mt], bhf[nt][1], bhf[nt][3]);
                    // Ah*Bl
                    mma16816(acc[mt][2 * nt],     ahf[mt], blf[nt][0], blf[nt][2]);
                    mma16816(acc[mt][2 * nt + 1], ahf[mt], blf[nt][1], blf[nt][3]);
                    // Al*Bh
                    mma16816(acc[mt][2 * nt],     alf[mt], bhf[nt][0], bhf[nt][2]);
                    mma16816(acc[mt][2 * nt + 1], alf[mt], bhf[nt][1], bhf[nt][3]);
                }
            }
        }

        __syncthreads();
        if (kt + 2 < NKT) load_stage(kt + 2);
    }

    // ---- epilogue: fragment layout -> global fp32 --------------------------
    #pragma unroll
    for (int mt = 0; mt < 2; ++mt) {
        const size_t row = mrow0 + wm * 32 + mt * 16 + (lid >> 2);
        #pragma unroll
        for (int nt = 0; nt < 4; ++nt) {
            #pragma unroll
            for (int n8 = 0; n8 < 2; ++n8) {
                const float* cc = acc[mt][2 * nt + n8];
                const size_t col = ncol0 + wn * 64 + nt * 16 + n8 * 8 + (lid & 3) * 2;
                *(float2*)(C + row * NCOL + col)       = make_float2(cc[0], cc[1]);
                *(float2*)(C + (row + 8) * NCOL + col) = make_float2(cc[2], cc[3]);
            }
        }
    }
}

// ============================================================================
// Kernel 2: sequential sLSTM recurrence (cluster-2 per head-half), with
// lin_x register prefetch and out-store hidden in the cluster-barrier window.
// ============================================================================
__global__ void __launch_bounds__(256, 1) __cluster_dims__(2, 1, 1)
slstm_rec(const float* __restrict__ Whh,   // [NH, 512, 128]
          const float* __restrict__ bias,  // [NH, 512]
          const float* __restrict__ linx,  // [T, B, 4096]
          float* __restrict__ out) {       // [T, B, 1024]
    __shared__ __align__(16) float hsh[2][4][HSZ];
    __shared__ float gsh[4][4][64];

    const int bx   = blockIdx.x;
    const int half = bx & 1;
    const int pair = bx >> 1;
    const int head = pair & 7;
    const int bg   = pair >> 3;

    const int t  = threadIdx.x;
    const int g  = t >> 6;
    const int dr = t & 63;
    const int k  = g * HSZ + half * 64 + dr;

    const float4* wv = (const float4*)(Whh + ((size_t)head * G4 + k) * HSZ);
    unsigned long long wp[64];
    #pragma unroll
    for (int q = 0; q < 32; ++q) {
        const float4 v = wv[q];
        wp[2 * q]     = pk(v.x, v.y);
        wp[2 * q + 1] = pk(v.z, v.w);
    }
    const float bk = bias[head * G4 + k];

    const int b2     = t >> 6;
    const int d      = t & 63;
    const int j      = half * 64 + d;
    const int bglob  = bg * 4 + b2;
    const int outcol = head * HSZ + j;

    for (int z = t; z < 2 * 4 * HSZ; z += 256) ((float*)hsh)[z] = 0.f;

    unsigned int lbase = (unsigned int)__cvta_generic_to_shared(&hsh[0][0][0]);
    unsigned int rbase;
    const unsigned int peer = (unsigned int)(half ^ 1);
    asm("mapa.shared::cluster.u32 %0, %1, %2;" : "=r"(rbase) : "r"(lbase), "r"(peer));

    float c_ = 0.f, m_ = 0.f, n_ = 0.f;

    asm volatile("barrier.cluster.arrive.aligned;" ::: "memory");
    asm volatile("barrier.cluster.wait.aligned;" ::: "memory");

    int cur = 0;
    const float* lxbase = linx + (size_t)(bg * 4) * NCOL + (size_t)head * G4 + k;
    const size_t lxstep = (size_t)BATCH * NCOL;

    // prologue prefetch: step 0
    float lx0 = __ldg(lxbase), lx1 = __ldg(lxbase + NCOL);
    float lx2 = __ldg(lxbase + 2 * NCOL), lx3 = __ldg(lxbase + 3 * NCOL);

    #pragma unroll 1
    for (int ts = 0; ts < T_STEPS; ++ts) {
        unsigned long long a0 = 0ull, a1 = 0ull, a2 = 0ull, a3 = 0ull;
        #pragma unroll
        for (int q4 = 0; q4 < 32; ++q4) {
            const ulonglong2 h0 = *(const ulonglong2*)&hsh[cur][0][q4 * 4];
            fma2(a0, wp[2 * q4], h0.x); fma2(a0, wp[2 * q4 + 1], h0.y);
            const ulonglong2 h1 = *(const ulonglong2*)&hsh[cur][1][q4 * 4];
            fma2(a1, wp[2 * q4], h1.x); fma2(a1, wp[2 * q4 + 1], h1.y);
            const ulonglong2 h2 = *(const ulonglong2*)&hsh[cur][2][q4 * 4];
            fma2(a2, wp[2 * q4], h2.x); fma2(a2, wp[2 * q4 + 1], h2.y);
            const ulonglong2 h3 = *(const ulonglong2*)&hsh[cur][3][q4 * 4];
            fma2(a3, wp[2 * q4], h3.x); fma2(a3, wp[2 * q4 + 1], h3.y);
        }
        const float2 s0 = upk(a0), s1 = upk(a1), s2 = upk(a2), s3 = upk(a3);
        gsh[g][0][dr] = s0.x + s0.y + lx0 + bk;
        gsh[g][1][dr] = s1.x + s1.y + lx1 + bk;
        gsh[g][2][dr] = s2.x + s2.y + lx2 + bk;
        gsh[g][3][dr] = s3.x + s3.y + lx3 + bk;
        __syncthreads();

        const float iv = gsh[0][b2][d];
        const float fv = gsh[1][b2][d];
        const float zv = gsh[2][b2][d];
        const float ov = gsh[3][b2][d];

        const float zt = 1.f - 2.f / (__expf(2.f * zv) + 1.f);   // tanh
        const float os = 1.f / (1.f + __expf(-ov));              // sigmoid
        const float fm = fv + m_;
        const float mn = fmaxf(fm, iv);
        const float ie = __expf(iv - mn);
        const float fe = __expf(fm - mn);
        c_ = fe * c_ + ie * zt;
        n_ = fe * n_ + ie;
        m_ = mn;
        const float h = os * (c_ / n_);

        const int nxt = cur ^ 1;
        hsh[nxt][b2][j] = h;
        const unsigned int roff =
            ((unsigned int)((nxt * 4 + b2) * HSZ + j)) * 4u;
        asm volatile("st.shared::cluster.f32 [%0], %1;"
                     :: "r"(rbase + roff), "f"(h) : "memory");

        asm volatile("barrier.cluster.arrive.aligned;" ::: "memory");

        // hide gmem traffic in the barrier window
        out[((size_t)ts * BATCH + bglob) * (NHEAD * HSZ) + outcol] = h;
        const int tn = (ts + 1 < T_STEPS) ? ts + 1 : ts;
        const float* lpn = lxbase + (size_t)tn * lxstep;
        lx0 = __ldg(lpn);            lx1 = __ldg(lpn + NCOL);
        lx2 = __ldg(lpn + 2 * NCOL); lx3 = __ldg(lpn + 3 * NCOL);

        asm volatile("barrier.cluster.wait.aligned;" ::: "memory");
        cur = nxt;
    }
}

// ============================================================================
extern "C" void kernel_launch(void* const* d_in, const int* in_sizes, int n_in,
                              void* d_out, int out_size) {
    const float* xs   = (const float*)d_in[0];  // [T, B, I]
    const float* wih  = (const float*)d_in[1];  // [NH, 4*HS, I]
    const float* whh  = (const float*)d_in[2];  // [NH, 4*HS, HS]
    const float* bias = (const float*)d_in[3];  // [NH, 4*HS]
    float* out = (float*)d_out;                 // [T, B, H]

    float *linx; __nv_bfloat16 *ah, *al, *bh, *bl;
    cudaGetSymbolAddress((void**)&linx, g_linx);
    cudaGetSymbolAddress((void**)&ah, g_ah);
    cudaGetSymbolAddress((void**)&al, g_al);
    cudaGetSymbolAddress((void**)&bh, g_bh);
    cudaGetSymbolAddress((void**)&bl, g_bl);

    cudaFuncSetAttribute(gemm3_hmma, cudaFuncAttributeMaxDynamicSharedMemorySize,
                         GEMM_SMEM);

    const size_t nA4 = (size_t)MROWS * KDIM / 4;
    const size_t nB4 = (size_t)NCOL * KDIM / 4;
    split_bf16<<<(unsigned)((nA4 + 255) / 256), 256>>>(xs, ah, al, nA4);
    split_bf16<<<(unsigned)((nB4 + 255) / 256), 256>>>(wih, bh, bl, nB4);

    dim3 gg(NCOL / 128, MROWS / 128);              // (32, 256)
    gemm3_hmma<<<gg, 256, GEMM_SMEM>>>(ah, al, bh, bl, linx);

    slstm_rec<<<128, 256>>>(whh, bias, linx, out);
}